// round 15
// baseline (speedup 1.0000x reference)
#include <cuda_runtime.h>
#include <cuda_bf16.h>
#include <cstdint>

#define NNODES 22
#define TB     500
#define BATCH  256
#define MROWS  (BATCH*NNODES)   // 5632
#define HOPP   512              // padded per-hop K stride
#define KBLK   1536             // per split-block K (3 hops x 512)
#define KTOT   4608             // B: [Wh | Wh | Wl]
#define KTOTA  3072             // A: [Xh | Xl]  (block 2 re-reads block 0)
#define NTOT   512              // padded N

#define BM 64
#define BN 128
#define BK 64
#define KT 72                   // K-chunks of 64 (over B's 4608)
#define KHALF 36                // chunks per split-K CTA
#define THREADS 128

typedef unsigned long long u64;

// ---------------- device scratch ------------------------------------------
__device__ __nv_bfloat16 g_Xbf[(size_t)MROWS*KTOTA];  // 34.6 MB
__device__ __nv_bfloat16 g_Wbf[(size_t)NTOT*KTOT];    // 4.7 MB
__device__ float         g_C0 [(size_t)MROWS*NTOT];   // 11.5 MB
__device__ float         g_C1 [(size_t)MROWS*NTOT];   // 11.5 MB

// ---------------------------------------------------------------------------
// Kernel 1: g_Xbf = bf16 split of [x | Ax | A2x], K-blocks [hi | lo]
// ---------------------------------------------------------------------------
__global__ __launch_bounds__(512) void build_xbf_kernel(
    const float* __restrict__ x, const float* __restrict__ adj)
{
    __shared__ float sA[NNODES*NNODES], sA2[NNODES*NNODES];
    const int tid = threadIdx.x;

    if (tid < NNODES) {
        float e[NNODES], mx = -1e30f;
        #pragma unroll
        for (int j = 0; j < NNODES; j++) mx = fmaxf(mx, adj[tid*NNODES + j]);
        float s = 0.f;
        #pragma unroll
        for (int j = 0; j < NNODES; j++) { e[j] = expf(adj[tid*NNODES + j] - mx); s += e[j]; }
        float inv = 1.f / s;
        #pragma unroll
        for (int j = 0; j < NNODES; j++) sA[tid*NNODES + j] = e[j] * inv;
    }
    __syncthreads();
    if (tid < NNODES*NNODES) {
        int n = tid / NNODES, m = tid - n*NNODES;
        float s = 0.f;
        #pragma unroll
        for (int k = 0; k < NNODES; k++) s = fmaf(sA[n*NNODES + k], sA[k*NNODES + m], s);
        sA2[tid] = s;
    }
    __syncthreads();

    const int b = blockIdx.x;
    const int t = tid;
    __nv_bfloat16* Xb = g_Xbf + (size_t)b * NNODES * KTOTA;

    if (t < TB) {
        float xv[NNODES];
        const float* xb = x + (size_t)b * NNODES * TB;
        #pragma unroll
        for (int m = 0; m < NNODES; m++) xv[m] = xb[m*TB + t];
        #pragma unroll
        for (int n = 0; n < NNODES; n++) {
            float h1 = 0.f, h2 = 0.f;
            #pragma unroll
            for (int m = 0; m < NNODES; m++) {
                h1 = fmaf(sA [n*NNODES + m], xv[m], h1);
                h2 = fmaf(sA2[n*NNODES + m], xv[m], h2);
            }
            float v0 = xv[n];
            __nv_bfloat16 hi0 = __float2bfloat16(v0);
            __nv_bfloat16 hi1 = __float2bfloat16(h1);
            __nv_bfloat16 hi2 = __float2bfloat16(h2);
            __nv_bfloat16 lo0 = __float2bfloat16(v0 - __bfloat162float(hi0));
            __nv_bfloat16 lo1 = __float2bfloat16(h1 - __bfloat162float(hi1));
            __nv_bfloat16 lo2 = __float2bfloat16(h2 - __bfloat162float(hi2));
            __nv_bfloat16* R = Xb + (size_t)n * KTOTA;
            R[t] = hi0;  R[HOPP + t] = hi1;  R[2*HOPP + t] = hi2;
            R[KBLK + t] = lo0;  R[KBLK + HOPP + t] = lo1;  R[KBLK + 2*HOPP + t] = lo2;
        }
    } else if (t < HOPP) {
        __nv_bfloat16 z = __float2bfloat16(0.f);
        #pragma unroll
        for (int n = 0; n < NNODES; n++) {
            __nv_bfloat16* R = Xb + (size_t)n * KTOTA;
            #pragma unroll
            for (int blk = 0; blk < 2; blk++)
                #pragma unroll
                for (int hop = 0; hop < 3; hop++)
                    R[blk*KBLK + hop*HOPP + t] = z;
        }
    }
}

// ---------------------------------------------------------------------------
// Kernel 2: g_Wbf[n][k] (K-major B), blocks [Wh | Wh | Wl]; 32x32 transpose.
// ---------------------------------------------------------------------------
__global__ __launch_bounds__(256) void build_wbf_kernel(const float* __restrict__ W) {
    __shared__ float sm[32][33];
    const int n0  = blockIdx.x * 32;
    const int tp0 = blockIdx.y * 32;
    const int hop = blockIdx.z;
    const int tx = threadIdx.x, ty0 = threadIdx.y;

    #pragma unroll
    for (int i = 0; i < 4; i++) {
        const int ty = ty0 + i*8;
        const int tp = tp0 + ty, n = n0 + tx;
        float v = 0.f;
        if (tp < TB && n < TB) v = W[((size_t)hop*TB + tp)*TB + n];
        sm[ty][tx] = v;
    }
    __syncthreads();

    #pragma unroll
    for (int i = 0; i < 4; i++) {
        const int ty = ty0 + i*8;
        const float vt = sm[tx][ty];
        __nv_bfloat16 hv = __float2bfloat16(vt);
        __nv_bfloat16 lv = __float2bfloat16(vt - __bfloat162float(hv));
        __nv_bfloat16* R = g_Wbf + (size_t)(n0 + ty) * KTOT + hop*HOPP + tp0 + tx;
        R[0]      = hv;
        R[KBLK]   = hv;
        R[2*KBLK] = lv;
    }
}

// ---------------------------------------------------------------------------
// Kernel 3: mma.sync bf16 GEMM, split-K x2 (R13-proven, unchanged)
// ---------------------------------------------------------------------------
__device__ __forceinline__ uint32_t sw128(int r, int c) {
    return (uint32_t)(r*128 + ((c ^ (r & 7)) << 4));
}
__device__ __forceinline__ uint32_t smem_u32(const void* p) {
    uint32_t a;
    asm("{ .reg .u64 t; cvta.to.shared.u64 t, %1; cvt.u32.u64 %0, t; }" : "=r"(a) : "l"(p));
    return a;
}
__device__ __forceinline__ void cp16(uint32_t dst, const void* src) {
    asm volatile("cp.async.cg.shared.global [%0], [%1], 16;" :: "r"(dst), "l"(src));
}
__device__ __forceinline__ void ldm_x4(uint32_t* q, uint32_t addr) {
    asm volatile("ldmatrix.sync.aligned.m8n8.x4.shared.b16 {%0,%1,%2,%3}, [%4];"
                 : "=r"(q[0]), "=r"(q[1]), "=r"(q[2]), "=r"(q[3]) : "r"(addr));
}
__device__ __forceinline__ void mma_bf16(float* c, const uint32_t* a, uint32_t b0, uint32_t b1) {
    asm volatile("mma.sync.aligned.m16n8k16.row.col.f32.bf16.bf16.f32 "
                 "{%0,%1,%2,%3}, {%4,%5,%6,%7}, {%8,%9}, {%0,%1,%2,%3};"
                 : "+f"(c[0]), "+f"(c[1]), "+f"(c[2]), "+f"(c[3])
                 : "r"(a[0]), "r"(a[1]), "r"(a[2]), "r"(a[3]), "r"(b0), "r"(b1));
}

#define A_ST 8192    // 64 rows * 128B
#define B_ST 16384   // 128 rows * 128B

__global__ void __launch_bounds__(THREADS, 3) gemm_mma_kernel() {
    __shared__ __align__(128) unsigned char smem[2*(A_ST + B_ST)];  // 48 KB

    const int tid  = threadIdx.x;
    const int lane = tid & 31;
    const int wn   = tid >> 5;
    const int row0 = blockIdx.y * BM;
    const int n0   = blockIdx.x * BN;
    const int z    = blockIdx.z;
    const int kb0  = z * KHALF;

    const uint32_t sA0 = smem_u32(smem);
    const uint32_t sB0 = sA0 + 2*A_ST;

    const char* gA = reinterpret_cast<const char*>(g_Xbf);
    const char* gB = reinterpret_cast<const char*>(g_Wbf);

    const int l_r = tid >> 3, l_c = tid & 7;
    const uint32_t aoff0 = sw128(l_r, l_c);
    const char* aptrb = gA + ((size_t)(row0 + l_r) * KTOTA + l_c*8) * 2;
    const char* bptrb = gB + ((size_t)(n0   + l_r) * KTOT  + l_c*8) * 2;
    const size_t A_RSTEP = (size_t)16 * KTOTA * 2;
    const size_t B_RSTEP = (size_t)16 * KTOT  * 2;

    float acc[4][4][4];
    #pragma unroll
    for (int i = 0; i < 4; i++)
        #pragma unroll
        for (int j = 0; j < 4; j++)
            #pragma unroll
            for (int q = 0; q < 4; q++) acc[i][j][q] = 0.f;

    {
        const int ak = (kb0 >= 48) ? kb0 - 48 : kb0;
        const size_t ab = (size_t)ak  * BK * 2;
        const size_t bb = (size_t)kb0 * BK * 2;
        #pragma unroll
        for (int i = 0; i < 4; i++) cp16(sA0 + aoff0 + i*2048, aptrb + i*A_RSTEP + ab);
        #pragma unroll
        for (int i = 0; i < 8; i++) cp16(sB0 + aoff0 + i*2048, bptrb + i*B_RSTEP + bb);
        asm volatile("cp.async.commit_group;" ::: "memory");
    }

    const int lr = lane & 15;
    const int lc = lane >> 4;

    uint32_t afr[2][4][4];
    uint32_t bfr[2][2][4];

    for (int it = 0; it < KHALF; it++) {
        asm volatile("cp.async.wait_group 0;" ::: "memory");
        __syncthreads();

        const int nit = it + 1;
        if (nit < KHALF) {
            const int ns = kb0 + nit;
            const int ans = (ns >= 48) ? ns - 48 : ns;
            const size_t ab = (size_t)ans * BK * 2;
            const size_t bb = (size_t)ns  * BK * 2;
            const uint32_t sa_l = sA0 + (nit & 1)*A_ST;
            const uint32_t sb_l = sB0 + (nit & 1)*B_ST;
            #pragma unroll
            for (int i = 0; i < 4; i++) cp16(sa_l + aoff0 + i*2048, aptrb + i*A_RSTEP + ab);
            #pragma unroll
            for (int i = 0; i < 8; i++) cp16(sb_l + aoff0 + i*2048, bptrb + i*B_RSTEP + bb);
            asm volatile("cp.async.commit_group;" ::: "memory");
        }

        const uint32_t sa = sA0 + (it & 1)*A_ST;
        const uint32_t sb = sB0 + (it & 1)*B_ST;

        {
            const int c = lc;
            #pragma unroll
            for (int mi = 0; mi < 4; mi++)
                ldm_x4(afr[0][mi], sa + sw128(mi*16 + lr, c));
            ldm_x4(bfr[0][0], sb + sw128(wn*32 +  0 + lr, c));
            ldm_x4(bfr[0][1], sb + sw128(wn*32 + 16 + lr, c));
        }
        #pragma unroll
        for (int ks = 0; ks < 4; ks++) {
            const int cur = ks & 1, nxt = cur ^ 1;
            if (ks < 3) {
                const int c = (ks+1)*2 + lc;
                #pragma unroll
                for (int mi = 0; mi < 4; mi++)
                    ldm_x4(afr[nxt][mi], sa + sw128(mi*16 + lr, c));
                ldm_x4(bfr[nxt][0], sb + sw128(wn*32 +  0 + lr, c));
                ldm_x4(bfr[nxt][1], sb + sw128(wn*32 + 16 + lr, c));
            }
            #pragma unroll
            for (int mi = 0; mi < 4; mi++) {
                mma_bf16(acc[mi][0], afr[cur][mi], bfr[cur][0][0], bfr[cur][0][2]);
                mma_bf16(acc[mi][1], afr[cur][mi], bfr[cur][0][1], bfr[cur][0][3]);
                mma_bf16(acc[mi][2], afr[cur][mi], bfr[cur][1][0], bfr[cur][1][2]);
                mma_bf16(acc[mi][3], afr[cur][mi], bfr[cur][1][1], bfr[cur][1][3]);
            }
        }
    }

    float* gC = (z == 0) ? g_C0 : g_C1;
    const int crow = lane >> 2;
    const int ccol = (lane & 3) * 2;
    #pragma unroll
    for (int mi = 0; mi < 4; mi++) {
        const int r = row0 + mi*16 + crow;
        #pragma unroll
        for (int ni = 0; ni < 4; ni++) {
            const int cbase = n0 + wn*32 + ni*8 + ccol;
            *reinterpret_cast<float2*>(&gC[(size_t)r      *NTOT + cbase]) =
                make_float2(acc[mi][ni][0], acc[mi][ni][1]);
            *reinterpret_cast<float2*>(&gC[(size_t)(r + 8)*NTOT + cbase]) =
                make_float2(acc[mi][ni][2], acc[mi][ni][3]);
        }
    }
}

// ---------------------------------------------------------------------------
// Kernel 4: replicate (R13 shape: high-occupancy, no smem) + __stcs + 2x ILP.
//   Block = 2 rows (m, m+1); 256 threads; each thread owns two float4 slots
//   per row spaced 64 apart -> full row covered by 128 threads x 2.
// ---------------------------------------------------------------------------
__global__ __launch_bounds__(256) void replicate_kernel(
    const float* __restrict__ bias, float* __restrict__ out, int E)
{
    const int half = threadIdx.x >> 7;            // 0 or 1: which row
    const int t4   = threadIdx.x & 63;            // first float4 slot (0..63)
    const int m = blockIdx.x * 2 + half;
    const int bb = m / NNODES, nn = m - bb*NNODES;

    // two float4 slots: t4 and t4+64 (t4+64 covers 64..124; 61..63 of the
    // second slot are out of range -> predicated)
    const int s0 = t4, s1 = t4 + 64;
    const bool p1 = (s1 < TB/4);

    const size_t ci = (size_t)m * NTOT;
    float4 a0 = *reinterpret_cast<const float4*>(&g_C0[ci + s0*4]);
    float4 b0 = *reinterpret_cast<const float4*>(&g_C1[ci + s0*4]);
    float4 c0 = *reinterpret_cast<const float4*>(&bias[s0*4]);
    float4 v0 = make_float4(a0.x + b0.x + c0.x, a0.y + b0.y + c0.y,
                            a0.z + b0.z + c0.z, a0.w + b0.w + c0.w);
    float4 v1 = make_float4(0.f, 0.f, 0.f, 0.f);
    if (p1) {
        float4 a1 = *reinterpret_cast<const float4*>(&g_C0[ci + s1*4]);
        float4 b1 = *reinterpret_cast<const float4*>(&g_C1[ci + s1*4]);
        float4 c1 = *reinterpret_cast<const float4*>(&bias[s1*4]);
        v1 = make_float4(a1.x + b1.x + c1.x, a1.y + b1.y + c1.y,
                         a1.z + b1.z + c1.z, a1.w + b1.w + c1.w);
    }

    float* p = out + (size_t)bb * E * (NNODES*TB) + (size_t)nn * TB;
    #pragma unroll 4
    for (int e = 0; e < E; e++) {
        __stcs(reinterpret_cast<float4*>(p + s0*4), v0);
        if (p1) __stcs(reinterpret_cast<float4*>(p + s1*4), v1);
        p += NNODES*TB;
    }
}

// ---------------------------------------------------------------------------
// Launch. Inputs: x, adj, W, b, emb_size.
// ---------------------------------------------------------------------------
extern "C" void kernel_launch(void* const* d_in, const int* in_sizes, int n_in,
                              void* d_out, int out_size) {
    const float* x    = (const float*)d_in[0];
    const float* adj  = (const float*)d_in[1];
    const float* Wmat = (const float*)d_in[2];
    const float* bias = (const float*)d_in[3];
    float* out = (float*)d_out;
    const int E = out_size / (BATCH * NNODES * TB);

    build_xbf_kernel<<<BATCH, 512>>>(x, adj);
    build_wbf_kernel<<<dim3(16, 16, 3), dim3(32, 8)>>>(Wmat);

    dim3 grid(NTOT / BN, MROWS / BM, 2);   // (4, 88, 2) = 704 CTAs
    gemm_mma_kernel<<<grid, THREADS>>>();

    replicate_kernel<<<MROWS/2, 256>>>(bias, out, E);
}

// round 16
// speedup vs baseline: 1.6534x; 1.6534x over previous
#include <cuda_runtime.h>
#include <cuda_fp16.h>
#include <cstdint>

#define NNODES 22
#define TB     500
#define BATCH  256
#define MROWS  (BATCH*NNODES)   // 5632
#define HOPP   512              // padded per-hop K stride
#define KF     1536             // K = 3 hops x 512 (single fp16 product)
#define NTOT   512              // padded N

#define BM 64
#define BN 128
#define BK 64
#define KCH 24                  // K-chunks of 64
#define KHALF 12                // chunks per split-K CTA
#define THREADS 128

typedef unsigned long long u64;

// ---------------- device scratch ------------------------------------------
__device__ __half g_Xfp[(size_t)MROWS*KF];   // 17.3 MB
__device__ __half g_Wfp[(size_t)NTOT*KF];    // 1.6 MB
__device__ float  g_C0 [(size_t)MROWS*NTOT]; // 11.5 MB
__device__ float  g_C1 [(size_t)MROWS*NTOT]; // 11.5 MB

// ---------------------------------------------------------------------------
// Kernel 1: g_Xfp = fp16 [x | Ax | A2x]; A = softmax(adj), A2 = A@A in smem.
// ---------------------------------------------------------------------------
__global__ __launch_bounds__(512) void build_xfp_kernel(
    const float* __restrict__ x, const float* __restrict__ adj)
{
    __shared__ float sA[NNODES*NNODES], sA2[NNODES*NNODES];
    const int tid = threadIdx.x;

    if (tid < NNODES) {
        float e[NNODES], mx = -1e30f;
        #pragma unroll
        for (int j = 0; j < NNODES; j++) mx = fmaxf(mx, adj[tid*NNODES + j]);
        float s = 0.f;
        #pragma unroll
        for (int j = 0; j < NNODES; j++) { e[j] = expf(adj[tid*NNODES + j] - mx); s += e[j]; }
        float inv = 1.f / s;
        #pragma unroll
        for (int j = 0; j < NNODES; j++) sA[tid*NNODES + j] = e[j] * inv;
    }
    __syncthreads();
    if (tid < NNODES*NNODES) {
        int n = tid / NNODES, m = tid - n*NNODES;
        float s = 0.f;
        #pragma unroll
        for (int k = 0; k < NNODES; k++) s = fmaf(sA[n*NNODES + k], sA[k*NNODES + m], s);
        sA2[tid] = s;
    }
    __syncthreads();

    const int b = blockIdx.x;
    const int t = tid;
    __half* Xb = g_Xfp + (size_t)b * NNODES * KF;

    if (t < TB) {
        float xv[NNODES];
        const float* xb = x + (size_t)b * NNODES * TB;
        #pragma unroll
        for (int m = 0; m < NNODES; m++) xv[m] = xb[m*TB + t];
        #pragma unroll
        for (int n = 0; n < NNODES; n++) {
            float h1 = 0.f, h2 = 0.f;
            #pragma unroll
            for (int m = 0; m < NNODES; m++) {
                h1 = fmaf(sA [n*NNODES + m], xv[m], h1);
                h2 = fmaf(sA2[n*NNODES + m], xv[m], h2);
            }
            __half* R = Xb + (size_t)n * KF;
            R[t]          = __float2half(xv[n]);
            R[HOPP + t]   = __float2half(h1);
            R[2*HOPP + t] = __float2half(h2);
        }
    } else if (t < HOPP) {   // t in [500, 512): zero padding columns
        __half z = __float2half(0.f);
        #pragma unroll
        for (int n = 0; n < NNODES; n++) {
            __half* R = Xb + (size_t)n * KF;
            #pragma unroll
            for (int hop = 0; hop < 3; hop++)
                R[hop*HOPP + t] = z;
        }
    }
}

// ---------------------------------------------------------------------------
// Kernel 2: g_Wfp[n][k] (K-major B) via 32x32 smem-transpose tiles.
//   grid (16 n-tiles, 16 tp-tiles, 3 hops), block (32, 8).
// ---------------------------------------------------------------------------
__global__ __launch_bounds__(256) void build_wfp_kernel(const float* __restrict__ W) {
    __shared__ float sm[32][33];
    const int n0  = blockIdx.x * 32;
    const int tp0 = blockIdx.y * 32;
    const int hop = blockIdx.z;
    const int tx = threadIdx.x, ty0 = threadIdx.y;

    #pragma unroll
    for (int i = 0; i < 4; i++) {
        const int ty = ty0 + i*8;
        const int tp = tp0 + ty, n = n0 + tx;
        float v = 0.f;
        if (tp < TB && n < TB) v = W[((size_t)hop*TB + tp)*TB + n];
        sm[ty][tx] = v;
    }
    __syncthreads();

    #pragma unroll
    for (int i = 0; i < 4; i++) {
        const int ty = ty0 + i*8;
        g_Wfp[(size_t)(n0 + ty) * KF + hop*HOPP + tp0 + tx] = __float2half(sm[tx][ty]);
    }
}

// ---------------------------------------------------------------------------
// Kernel 3: mma.sync fp16 GEMM, split-K x2: CTA z does chunks [z*12, z*12+12).
//   block 64x128x64, 128 thr, 2-stage cp.async, reg frag double-buffer.
//   grid (4, 88, 2) = 704 CTAs.
// ---------------------------------------------------------------------------
__device__ __forceinline__ uint32_t sw128(int r, int c) {
    return (uint32_t)(r*128 + ((c ^ (r & 7)) << 4));
}
__device__ __forceinline__ uint32_t smem_u32(const void* p) {
    uint32_t a;
    asm("{ .reg .u64 t; cvta.to.shared.u64 t, %1; cvt.u32.u64 %0, t; }" : "=r"(a) : "l"(p));
    return a;
}
__device__ __forceinline__ void cp16(uint32_t dst, const void* src) {
    asm volatile("cp.async.cg.shared.global [%0], [%1], 16;" :: "r"(dst), "l"(src));
}
__device__ __forceinline__ void ldm_x4(uint32_t* q, uint32_t addr) {
    asm volatile("ldmatrix.sync.aligned.m8n8.x4.shared.b16 {%0,%1,%2,%3}, [%4];"
                 : "=r"(q[0]), "=r"(q[1]), "=r"(q[2]), "=r"(q[3]) : "r"(addr));
}
__device__ __forceinline__ void mma_f16(float* c, const uint32_t* a, uint32_t b0, uint32_t b1) {
    asm volatile("mma.sync.aligned.m16n8k16.row.col.f32.f16.f16.f32 "
                 "{%0,%1,%2,%3}, {%4,%5,%6,%7}, {%8,%9}, {%0,%1,%2,%3};"
                 : "+f"(c[0]), "+f"(c[1]), "+f"(c[2]), "+f"(c[3])
                 : "r"(a[0]), "r"(a[1]), "r"(a[2]), "r"(a[3]), "r"(b0), "r"(b1));
}

#define A_ST 8192    // 64 rows * 128B
#define B_ST 16384   // 128 rows * 128B

__global__ void __launch_bounds__(THREADS, 3) gemm_mma_kernel() {
    __shared__ __align__(128) unsigned char smem[2*(A_ST + B_ST)];  // 48 KB

    const int tid  = threadIdx.x;
    const int lane = tid & 31;
    const int wn   = tid >> 5;
    const int row0 = blockIdx.y * BM;
    const int n0   = blockIdx.x * BN;
    const int z    = blockIdx.z;
    const int kb0  = z * KHALF;

    const uint32_t sA0 = smem_u32(smem);
    const uint32_t sB0 = sA0 + 2*A_ST;

    const char* gA = reinterpret_cast<const char*>(g_Xfp);
    const char* gB = reinterpret_cast<const char*>(g_Wfp);

    const int l_r = tid >> 3, l_c = tid & 7;
    const uint32_t aoff0 = sw128(l_r, l_c);
    const char* aptrb = gA + ((size_t)(row0 + l_r) * KF + l_c*8) * 2;
    const char* bptrb = gB + ((size_t)(n0   + l_r) * KF + l_c*8) * 2;
    const size_t A_RSTEP = (size_t)16 * KF * 2;
    const size_t B_RSTEP = (size_t)16 * KF * 2;

    float acc[4][4][4];
    #pragma unroll
    for (int i = 0; i < 4; i++)
        #pragma unroll
        for (int j = 0; j < 4; j++)
            #pragma unroll
            for (int q = 0; q < 4; q++) acc[i][j][q] = 0.f;

    {
        const size_t kb = (size_t)kb0 * BK * 2;
        #pragma unroll
        for (int i = 0; i < 4; i++) cp16(sA0 + aoff0 + i*2048, aptrb + i*A_RSTEP + kb);
        #pragma unroll
        for (int i = 0; i < 8; i++) cp16(sB0 + aoff0 + i*2048, bptrb + i*B_RSTEP + kb);
        asm volatile("cp.async.commit_group;" ::: "memory");
    }

    const int lr = lane & 15;
    const int lc = lane >> 4;

    uint32_t afr[2][4][4];
    uint32_t bfr[2][2][4];

    for (int it = 0; it < KHALF; it++) {
        asm volatile("cp.async.wait_group 0;" ::: "memory");
        __syncthreads();

        const int nit = it + 1;
        if (nit < KHALF) {
            const size_t kb = (size_t)(kb0 + nit) * BK * 2;
            const uint32_t sa_l = sA0 + (nit & 1)*A_ST;
            const uint32_t sb_l = sB0 + (nit & 1)*B_ST;
            #pragma unroll
            for (int i = 0; i < 4; i++) cp16(sa_l + aoff0 + i*2048, aptrb + i*A_RSTEP + kb);
            #pragma unroll
            for (int i = 0; i < 8; i++) cp16(sb_l + aoff0 + i*2048, bptrb + i*B_RSTEP + kb);
            asm volatile("cp.async.commit_group;" ::: "memory");
        }

        const uint32_t sa = sA0 + (it & 1)*A_ST;
        const uint32_t sb = sB0 + (it & 1)*B_ST;

        {
            const int c = lc;
            #pragma unroll
            for (int mi = 0; mi < 4; mi++)
                ldm_x4(afr[0][mi], sa + sw128(mi*16 + lr, c));
            ldm_x4(bfr[0][0], sb + sw128(wn*32 +  0 + lr, c));
            ldm_x4(bfr[0][1], sb + sw128(wn*32 + 16 + lr, c));
        }
        #pragma unroll
        for (int ks = 0; ks < 4; ks++) {
            const int cur = ks & 1, nxt = cur ^ 1;
            if (ks < 3) {
                const int c = (ks+1)*2 + lc;
                #pragma unroll
                for (int mi = 0; mi < 4; mi++)
                    ldm_x4(afr[nxt][mi], sa + sw128(mi*16 + lr, c));
                ldm_x4(bfr[nxt][0], sb + sw128(wn*32 +  0 + lr, c));
                ldm_x4(bfr[nxt][1], sb + sw128(wn*32 + 16 + lr, c));
            }
            #pragma unroll
            for (int mi = 0; mi < 4; mi++) {
                mma_f16(acc[mi][0], afr[cur][mi], bfr[cur][0][0], bfr[cur][0][2]);
                mma_f16(acc[mi][1], afr[cur][mi], bfr[cur][0][1], bfr[cur][0][3]);
                mma_f16(acc[mi][2], afr[cur][mi], bfr[cur][1][0], bfr[cur][1][2]);
                mma_f16(acc[mi][3], afr[cur][mi], bfr[cur][1][1], bfr[cur][1][3]);
            }
        }
    }

    float* gC = (z == 0) ? g_C0 : g_C1;
    const int crow = lane >> 2;
    const int ccol = (lane & 3) * 2;
    #pragma unroll
    for (int mi = 0; mi < 4; mi++) {
        const int r = row0 + mi*16 + crow;
        #pragma unroll
        for (int ni = 0; ni < 4; ni++) {
            const int cbase = n0 + wn*32 + ni*8 + ccol;
            *reinterpret_cast<float2*>(&gC[(size_t)r      *NTOT + cbase]) =
                make_float2(acc[mi][ni][0], acc[mi][ni][1]);
            *reinterpret_cast<float2*>(&gC[(size_t)(r + 8)*NTOT + cbase]) =
                make_float2(acc[mi][ni][2], acc[mi][ni][3]);
        }
    }
}

// ---------------------------------------------------------------------------
// Kernel 4: replicate — R13-proven version, byte-for-byte. Do not touch.
// ---------------------------------------------------------------------------
__global__ __launch_bounds__(256) void replicate_kernel(
    const float* __restrict__ bias, float* __restrict__ out, int E)
{
    const int half = threadIdx.x >> 7;
    const int t4   = threadIdx.x & 127;
    const int m = blockIdx.x * 2 + half;
    if (t4 >= TB/4) return;
    const int bb = m / NNODES, nn = m - bb*NNODES;
    float4 v0 = *reinterpret_cast<const float4*>(&g_C0[(size_t)m*NTOT + t4*4]);
    float4 v1 = *reinterpret_cast<const float4*>(&g_C1[(size_t)m*NTOT + t4*4]);
    float4 bv = *reinterpret_cast<const float4*>(&bias[t4*4]);
    float4 v = make_float4(v0.x + v1.x + bv.x, v0.y + v1.y + bv.y,
                           v0.z + v1.z + bv.z, v0.w + v1.w + bv.w);
    float* p = out + (size_t)bb * E * (NNODES*TB) + (size_t)nn * TB + t4*4;
    #pragma unroll 4
    for (int e = 0; e < E; e++) {
        *reinterpret_cast<float4*>(p) = v;
        p += NNODES*TB;
    }
}

// ---------------------------------------------------------------------------
// Launch. Inputs: x, adj, W, b, emb_size.
// ---------------------------------------------------------------------------
extern "C" void kernel_launch(void* const* d_in, const int* in_sizes, int n_in,
                              void* d_out, int out_size) {
    const float* x    = (const float*)d_in[0];
    const float* adj  = (const float*)d_in[1];
    const float* Wmat = (const float*)d_in[2];
    const float* bias = (const float*)d_in[3];
    float* out = (float*)d_out;
    const int E = out_size / (BATCH * NNODES * TB);

    build_xfp_kernel<<<BATCH, 512>>>(x, adj);
    build_wfp_kernel<<<dim3(16, 16, 3), dim3(32, 8)>>>(Wmat);

    dim3 grid(NTOT / BN, MROWS / BM, 2);   // (4, 88, 2) = 704 CTAs
    gemm_mma_kernel<<<grid, THREADS>>>();

    replicate_kernel<<<MROWS/2, 256>>>(bias, out, E);
}